// round 11
// baseline (speedup 1.0000x reference)
#include <cuda_runtime.h>
#include <cuda_fp16.h>
#include <cstdint>
#include <math.h>

// ---------------- problem constants ----------------
#define T_TOK 2048
#define HDIM  2048
#define FDIM  5504
#define EEXP  8

// ---------------- device scratch (static, no allocation) ----------------
__device__ int   g_cnt[EEXP];
__device__ int   g_ptok[EEXP * T_TOK];
__device__ float g_pw[EEXP * T_TOK];

#define GAELEM ((size_t)EEXP * (size_t)T_TOK * (size_t)HDIM)
#define HBELEM ((size_t)EEXP * (size_t)T_TOK * (size_t)FDIM)
__device__ __align__(16) __half g_gah[GAELEM]; // gathered x (fp16)
__device__ __align__(16) __half g_hbh[HBELEM]; // silu(g)*u (fp16)

// ---------------- PTX helpers ----------------
__device__ __forceinline__ uint32_t smem_u32(const void* p) {
    uint32_t a;
    asm("{ .reg .u64 t; cvta.to.shared.u64 t, %1; cvt.u32.u64 %0, t; }"
        : "=r"(a) : "l"(p));
    return a;
}

__device__ __forceinline__ void cpa16(uint32_t dst, const void* src) {
    asm volatile("cp.async.cg.shared.global [%0], [%1], 16;"
                 :: "r"(dst), "l"(src) : "memory");
}

#define MBAR_INIT(addr, cnt) \
    asm volatile("mbarrier.init.shared.b64 [%0], %1;" :: "r"(addr), "r"(cnt) : "memory")
#define MBAR_ARRIVE(addr) \
    asm volatile("mbarrier.arrive.shared.b64 _, [%0];" :: "r"(addr) : "memory")
// arrive (counted against the INIT count: .noinc) on completion of this
// thread's prior cp.async ops
#define MBAR_CPA_ARRIVE(addr) \
    asm volatile("cp.async.mbarrier.arrive.noinc.shared.b64 [%0];" :: "r"(addr) : "memory")
#define MBAR_WAIT(addr, par) do {                                             \
    uint32_t _m = (addr); uint32_t _p = (par); uint32_t _d;                   \
    asm volatile("{\n\t.reg .pred p;\n\t"                                     \
        "mbarrier.try_wait.parity.shared.b64 p, [%1], %2;\n\t"                \
        "selp.b32 %0, 1, 0, p;\n\t}"                                          \
        : "=r"(_d) : "r"(_m), "r"(_p) : "memory");                            \
    if (!_d) {                                                                \
        asm volatile("{\n\t.reg .pred P1;\n\t"                                \
            "WL_%=:\n\t"                                                      \
            "mbarrier.try_wait.parity.shared.b64 P1, [%0], %1;\n\t"           \
            "@P1 bra.uni WD_%=;\n\t"                                          \
            "bra.uni WL_%=;\n\t"                                              \
            "WD_%=:\n\t}"                                                     \
            :: "r"(_m), "r"(_p) : "memory");                                  \
    }                                                                         \
} while (0)

__device__ __forceinline__ void ldsm4(uint32_t* r, uint32_t addr) {
    asm volatile("ldmatrix.sync.aligned.m8n8.x4.shared.b16 {%0,%1,%2,%3}, [%4];"
                 : "=r"(r[0]), "=r"(r[1]), "=r"(r[2]), "=r"(r[3]) : "r"(addr));
}

__device__ __forceinline__ void mma16816(float* c, const uint32_t* a, const uint32_t* b) {
    asm volatile(
        "mma.sync.aligned.m16n8k16.row.col.f32.f16.f16.f32 "
        "{%0,%1,%2,%3}, {%4,%5,%6,%7}, {%8,%9}, {%0,%1,%2,%3};"
        : "+f"(c[0]), "+f"(c[1]), "+f"(c[2]), "+f"(c[3])
        : "r"(a[0]), "r"(a[1]), "r"(a[2]), "r"(a[3]), "r"(b[0]), "r"(b[1]));
}

// ---------------- kernel 0: zero counters ----------------
__global__ void zero_cnt_kernel() {
    if (threadIdx.x < EEXP) g_cnt[threadIdx.x] = 0;
}

// ---------------- kernel 1: router (fp32, exact top-k) ----------------
__global__ void __launch_bounds__(256) router_kernel(const float* __restrict__ x,
                                                     const float* __restrict__ rw) {
    int t = blockIdx.x;
    int warp = threadIdx.x >> 5;
    int lane = threadIdx.x & 31;
    __shared__ float logits[EEXP];

    const float* xr = x + (size_t)t * HDIM;
    const float* wr = rw + (size_t)warp * HDIM;
    float s = 0.f;
    for (int h = lane * 4; h < HDIM; h += 128) {
        float4 xv = *(const float4*)(xr + h);
        float4 wv = *(const float4*)(wr + h);
        s = fmaf(xv.x, wv.x, s);
        s = fmaf(xv.y, wv.y, s);
        s = fmaf(xv.z, wv.z, s);
        s = fmaf(xv.w, wv.w, s);
    }
    #pragma unroll
    for (int o = 16; o; o >>= 1) s += __shfl_down_sync(0xffffffffu, s, o);
    if (lane == 0) logits[warp] = s;
    __syncthreads();

    if (threadIdx.x == 0) {
        int i0 = 0; float v0 = logits[0];
        #pragma unroll
        for (int i = 1; i < EEXP; i++)
            if (logits[i] > v0) { v0 = logits[i]; i0 = i; }
        int i1 = -1; float v1 = -3.0e38f;
        #pragma unroll
        for (int i = 0; i < EEXP; i++) {
            if (i == i0) continue;
            if (logits[i] > v1) { v1 = logits[i]; i1 = i; }
        }
        float e1 = expf(v1 - v0);
        float inv = 1.f / (1.f + e1);
        int s0 = atomicAdd(&g_cnt[i0], 1);
        g_ptok[i0 * T_TOK + s0] = t;
        g_pw  [i0 * T_TOK + s0] = inv;
        int s1 = atomicAdd(&g_cnt[i1], 1);
        g_ptok[i1 * T_TOK + s1] = t;
        g_pw  [i1 * T_TOK + s1] = e1 * inv;
    }
}

// ---------------- kernel 2: gather tokens -> fp16 ----------------
__global__ void __launch_bounds__(128) gather_x_kernel(const float* __restrict__ x) {
    int row = blockIdx.x;                 // e*T_TOK + slot
    int e = row >> 11;
    int slot = row & (T_TOK - 1);
    if (slot >= g_cnt[e]) return;
    const float4* src = (const float4*)(x + (size_t)g_ptok[row] * HDIM);
    size_t ob = (size_t)row * HDIM;
    for (int i = threadIdx.x; i < HDIM / 4; i += 128) {
        float4 v = src[i];
        __half2 h0 = __floats2half2_rn(v.x, v.y);
        __half2 h1 = __floats2half2_rn(v.z, v.w);
        *(__half2*)(g_gah + ob + i * 4)     = h0;
        *(__half2*)(g_gah + ob + i * 4 + 2) = h1;
    }
}

// ---------------- GEMM pipeline layout ----------------
// CTA tile 128(M) x 256(B rows); stage (48KB): A fp16 16K @0 | B fp16 32K @16384
// 4 stages = 196608; barriers @196608: full[4] (+0..24), empty[4] (+32..56)
#define STGSZ   49152u
#define NST     4
#define BAR_OFF 196608u
#define SMEM_GEMM 196864
#define BAR_FULL(sb, s)  ((sb) + BAR_OFF + (uint32_t)(s) * 8)
#define BAR_EMPTY(sb, s) ((sb) + BAR_OFF + 32 + (uint32_t)(s) * 8)

// cp.async a 128x64 fp16 A tile into SW128-swizzled smem (256 threads)
__device__ __forceinline__ void cpa_tileA(uint32_t base,
                                          const __half* __restrict__ A,
                                          size_t stride, int k0, int tid) {
    #pragma unroll
    for (int i = 0; i < 4; i++) {
        int flat = tid + (i << 8);
        int r = flat >> 3, u = flat & 7;
        uint32_t dst = base + r * 128 + ((u ^ (r & 7)) << 4);
        size_t off = (size_t)r * stride + k0 + u * 8;
        cpa16(dst, A + off);
    }
}

// store pre-converted fp16 uint2 regs into swizzled B tile (256 rows).
// IL: interleave gate/up rows: smem row = 2*r (gate, r<128) / 2*(r-128)+1 (up)
template <bool IL>
__device__ __forceinline__ void sts_B(char* sm, uint32_t sboff, const uint2* br, int tid) {
    #pragma unroll
    for (int i = 0; i < 16; i++) {
        int flat = tid + (i << 8);
        int row = flat >> 4, c4 = flat & 15;
        int sr = IL ? ((row < 128) ? (row << 1) : (((row - 128) << 1) + 1)) : row;
        uint32_t off = sboff + sr * 128 + (((c4 >> 1) ^ (sr & 7)) << 4) + ((c4 & 1) << 3);
        *(uint2*)(sm + off) = br[i];
    }
}

// two k16 steps of single-pass fp16 MMA over a 64x64 warp tile
__device__ __forceinline__ void mma_half(uint32_t Ab, uint32_t Bb, int kk0,
                                         int wm, int wn, int lane,
                                         float (&acc)[4][8][4]) {
    #pragma unroll
    for (int ks = 0; ks < 2; ks++) {
        int kk = kk0 + ks * 16;
        uint32_t ah[4][4], bh[8][2];
        int lrow = lane & 15;
        int au = (kk >> 3) + (lane >> 4);          // A smem unit
        #pragma unroll
        for (int mi = 0; mi < 4; mi++) {
            int r = wm * 64 + mi * 16 + lrow;
            uint32_t ad = Ab + r * 128 + ((au ^ (r & 7)) << 4);
            ldsm4(ah[mi], ad);
        }
        int bu = (kk >> 3) + ((lane >> 3) & 1);    // B smem unit
        #pragma unroll
        for (int bi = 0; bi < 4; bi++) {
            int nr = wn * 64 + bi * 16 + ((lane >> 4) << 3) + (lane & 7);
            uint32_t bd = Bb + nr * 128 + ((bu ^ (nr & 7)) << 4);
            uint32_t t[4];
            ldsm4(t, bd);
            bh[2 * bi][0] = t[0]; bh[2 * bi][1] = t[1];
            bh[2 * bi + 1][0] = t[2]; bh[2 * bi + 1][1] = t[3];
        }
        #pragma unroll
        for (int mi = 0; mi < 4; mi++)
            #pragma unroll
            for (int ni = 0; ni < 8; ni++)
                mma16816(acc[mi][ni], ah[mi], bh[ni]);
    }
}

// B fp32 loads converted to fp16 at load time (16 uint2 per thread)
__device__ __forceinline__ uint2 cvt_u2(float4 v) {
    __half2 h0 = __floats2half2_rn(v.x, v.y);
    __half2 h1 = __floats2half2_rn(v.z, v.w);
    return make_uint2(*(uint32_t*)&h0, *(uint32_t*)&h1);
}
// gemm1 variant: rows 0..127 gate, 128..255 up
__device__ __forceinline__ void ldg_B1(uint2* br, const float* __restrict__ gwB,
                                       const float* __restrict__ uwB, int k0, int tid) {
    #pragma unroll
    for (int i = 0; i < 16; i++) {
        int flat = tid + (i << 8);
        int row = flat >> 4, c4 = flat & 15;
        const float* s = (row < 128) ? (gwB + (size_t)row * HDIM)
                                     : (uwB + (size_t)(row - 128) * HDIM);
        br[i] = cvt_u2(*(const float4*)(s + k0 + c4 * 4));
    }
}
// gemm2 variant (down_w, 256 rows)
__device__ __forceinline__ void ldg_B2(uint2* br, const float* __restrict__ dwB,
                                       int k0, int tid) {
    #pragma unroll
    for (int i = 0; i < 16; i++) {
        int flat = tid + (i << 8);
        int row = flat >> 4, c4 = flat & 15;
        br[i] = cvt_u2(*(const float4*)(dwB + (size_t)row * FDIM + k0 + c4 * 4));
    }
}

// ---------------- kernel 3: gate/up GEMM (mbarrier pipeline) + SiLU ----------------
// CTA tile 128 x 128f (256 interleaved B rows); 256 threads dual-role
__global__ void __launch_bounds__(256, 1) gemm1_kernel(const float* __restrict__ gw,
                                                       const float* __restrict__ uw) {
    extern __shared__ char sm[];
    uint32_t sb = smem_u32(sm);
    int e = blockIdx.z;
    int cnt = g_cnt[e];
    int m0 = blockIdx.x << 7;
    if (m0 >= cnt) return;
    int n0f = blockIdx.y << 7;   // 128 f per CTA
    int tid = threadIdx.x, lane = tid & 31, wid = tid >> 5;
    int wm = wid & 1, wn = wid >> 1;   // warp tile 64x64
    const int NC = HDIM / 64;   // 32

    if (tid == 0) {
        #pragma unroll
        for (int s = 0; s < NST; s++) {
            MBAR_INIT(BAR_FULL(sb, s), 512);   // 256 noinc cp.async arrives + 256 sts arrives
            MBAR_INIT(BAR_EMPTY(sb, s), 8);    // 8 consuming warps
        }
    }
    __syncthreads();

    const __half* A = g_gah + ((size_t)e * T_TOK + m0) * HDIM;
    const float* gwB = gw + ((size_t)e * FDIM + n0f) * HDIM;
    const float* uwB = uw + ((size_t)e * FDIM + n0f) * HDIM;

    float acc[4][8][4];
    #pragma unroll
    for (int a = 0; a < 4; a++)
        #pragma unroll
        for (int b = 0; b < 8; b++)
            #pragma unroll
            for (int c = 0; c < 4; c++) acc[a][b][c] = 0.f;

    uint2 br[16];
    ldg_B1(br, gwB, uwB, 0, tid);

    int ps = 0, pph = 1;   // producer cursor
    int cs = 0, cph = 0;   // consumer cursor
    for (int c = 0; c < NC + 2; c++) {
        uint32_t Ab = sb + cs * STGSZ;
        uint32_t Bb = Ab + 16384u;
        if (c >= 2) {
            MBAR_WAIT(BAR_FULL(sb, cs), cph);
            mma_half(Ab, Bb, 0, wm, wn, lane, acc);
        }
        if (c < NC) {
            MBAR_WAIT(BAR_EMPTY(sb, ps), pph);
            uint32_t base = sb + ps * STGSZ;
            cpa_tileA(base, A, HDIM, c << 6, tid);
            MBAR_CPA_ARRIVE(BAR_FULL(sb, ps));
            sts_B<true>(sm, ps * STGSZ + 16384u, br, tid);
            MBAR_ARRIVE(BAR_FULL(sb, ps));
            if (++ps == NST) { ps = 0; pph ^= 1; }
            if (c + 1 < NC) ldg_B1(br, gwB, uwB, (c + 1) << 6, tid);
        }
        if (c >= 2) {
            mma_half(Ab, Bb, 32, wm, wn, lane, acc);
            __syncwarp();
            if (lane == 0) MBAR_ARRIVE(BAR_EMPTY(sb, cs));
            if (++cs == NST) { cs = 0; cph ^= 1; }
        }
    }

    // epilogue: acc cols (c0,c1) = (gate_j, up_j); h = silu(g)*u -> fp16
    #pragma unroll
    for (int mi = 0; mi < 4; mi++)
        #pragma unroll
        for (int rh = 0; rh < 2; rh++) {
            int row = wm * 64 + mi * 16 + (lane >> 2) + rh * 8;
            int slot = m0 + row;
            if (slot < cnt) {
                size_t hb = ((size_t)e * T_TOK + slot) * FDIM + n0f;
                #pragma unroll
                for (int ni = 0; ni < 8; ni++) {
                    float g = acc[mi][ni][rh * 2 + 0];
                    float u = acc[mi][ni][rh * 2 + 1];
                    float h = u * g / (1.f + __expf(-g));
                    int j = wn * 32 + ni * 4 + (lane & 3);
                    g_hbh[hb + j] = __float2half_rn(h);
                }
            }
        }
}

// ---------------- kernel 4: down GEMM (mbarrier pipeline) + weighted scatter ----------------
// CTA tile 128 x 256; 256 threads dual-role
__global__ void __launch_bounds__(256, 1) gemm2_kernel(const float* __restrict__ dw,
                                                       float* __restrict__ out) {
    extern __shared__ char sm[];
    uint32_t sb = smem_u32(sm);
    int e = blockIdx.z;
    int cnt = g_cnt[e];
    int m0 = blockIdx.x << 7;
    if (m0 >= cnt) return;
    int n0 = blockIdx.y << 8;   // 256 h-cols per CTA
    int tid = threadIdx.x, lane = tid & 31, wid = tid >> 5;
    int wm = wid & 1, wn = wid >> 1;
    const int NC = FDIM / 64;   // 86

    if (tid == 0) {
        #pragma unroll
        for (int s = 0; s < NST; s++) {
            MBAR_INIT(BAR_FULL(sb, s), 512);
            MBAR_INIT(BAR_EMPTY(sb, s), 8);
        }
    }
    __syncthreads();

    const __half* A = g_hbh + ((size_t)e * T_TOK + m0) * FDIM;
    const float* dwB = dw + ((size_t)e * HDIM + n0) * FDIM;

    float acc[4][8][4];
    #pragma unroll
    for (int a = 0; a < 4; a++)
        #pragma unroll
        for (int b = 0; b < 8; b++)
            #pragma unroll
            for (int c = 0; c < 4; c++) acc[a][b][c] = 0.f;

    uint2 br[16];
    ldg_B2(br, dwB, 0, tid);

    int ps = 0, pph = 1;
    int cs = 0, cph = 0;
    for (int c = 0; c < NC + 2; c++) {
        uint32_t Ab = sb + cs * STGSZ;
        uint32_t Bb = Ab + 16384u;
        if (c >= 2) {
            MBAR_WAIT(BAR_FULL(sb, cs), cph);
            mma_half(Ab, Bb, 0, wm, wn, lane, acc);
        }
        if (c < NC) {
            MBAR_WAIT(BAR_EMPTY(sb, ps), pph);
            uint32_t base = sb + ps * STGSZ;
            cpa_tileA(base, A, FDIM, c << 6, tid);
            MBAR_CPA_ARRIVE(BAR_FULL(sb, ps));
            sts_B<false>(sm, ps * STGSZ + 16384u, br, tid);
            MBAR_ARRIVE(BAR_FULL(sb, ps));
            if (++ps == NST) { ps = 0; pph ^= 1; }
            if (c + 1 < NC) ldg_B2(br, dwB, (c + 1) << 6, tid);
        }
        if (c >= 2) {
            mma_half(Ab, Bb, 32, wm, wn, lane, acc);
            __syncwarp();
            if (lane == 0) MBAR_ARRIVE(BAR_EMPTY(sb, cs));
            if (++cs == NST) { cs = 0; cph ^= 1; }
        }
    }

    // epilogue: weighted atomic scatter to out
    #pragma unroll
    for (int mi = 0; mi < 4; mi++)
        #pragma unroll
        for (int rh = 0; rh < 2; rh++) {
            int row = wm * 64 + mi * 16 + (lane >> 2) + rh * 8;
            int slot = m0 + row;
            if (slot < cnt) {
                int tok = g_ptok[e * T_TOK + slot];
                float w = g_pw[e * T_TOK + slot];
                float* orow = out + (size_t)tok * HDIM + n0;
                #pragma unroll
                for (int ni = 0; ni < 8; ni++) {
                    int col = wn * 64 + ni * 8 + 2 * (lane & 3);
                    atomicAdd(orow + col,     acc[mi][ni][rh * 2 + 0] * w);
                    atomicAdd(orow + col + 1, acc[mi][ni][rh * 2 + 1] * w);
                }
            }
        }
}

// ---------------- launch ----------------
extern "C" void kernel_launch(void* const* d_in, const int* in_sizes, int n_in,
                              void* d_out, int out_size) {
    const float* x  = (const float*)d_in[0];   // [B,S,H]
    const float* rw = (const float*)d_in[1];   // [E,H]
    const float* gw = (const float*)d_in[2];   // [E,F,H]
    const float* uw = (const float*)d_in[3];   // [E,F,H]
    const float* dw = (const float*)d_in[4];   // [E,H,F]
    float* out = (float*)d_out;

    cudaFuncSetAttribute(gemm1_kernel, cudaFuncAttributeMaxDynamicSharedMemorySize, SMEM_GEMM);
    cudaFuncSetAttribute(gemm2_kernel, cudaFuncAttributeMaxDynamicSharedMemorySize, SMEM_GEMM);

    cudaMemsetAsync(out, 0, (size_t)out_size * sizeof(float));
    zero_cnt_kernel<<<1, 32>>>();
    router_kernel<<<T_TOK, 256>>>(x, rw);
    gather_x_kernel<<<EEXP * T_TOK, 128>>>(x);
    gemm1_kernel<<<dim3(16, FDIM / 128, EEXP), 256, SMEM_GEMM>>>(gw, uw);
    gemm2_kernel<<<dim3(16, HDIM / 256, EEXP), 256, SMEM_GEMM>>>(dw, out);
}

// round 12
// speedup vs baseline: 1.0233x; 1.0233x over previous
#include <cuda_runtime.h>
#include <cuda_fp16.h>
#include <cstdint>
#include <math.h>

// ---------------- problem constants ----------------
#define T_TOK 2048
#define HDIM  2048
#define FDIM  5504
#define EEXP  8

// ---------------- device scratch (static, no allocation) ----------------
__device__ int   g_cnt[EEXP];
__device__ int   g_ptok[EEXP * T_TOK];
__device__ float g_pw[EEXP * T_TOK];

#define WELEM  ((size_t)EEXP * (size_t)FDIM * (size_t)HDIM)
#define GAELEM ((size_t)EEXP * (size_t)T_TOK * (size_t)HDIM)
#define HBELEM ((size_t)EEXP * (size_t)T_TOK * (size_t)FDIM)
__device__ __align__(16) __half g_gwh[WELEM];  // gate w fp16 [E,F,H]
__device__ __align__(16) __half g_uwh[WELEM];  // up   w fp16 [E,F,H]
__device__ __align__(16) __half g_dwh[WELEM];  // down w fp16 [E,H,F]
__device__ __align__(16) __half g_gah[GAELEM]; // gathered x (fp16)
__device__ __align__(16) __half g_hbh[HBELEM]; // silu(g)*u (fp16)

// ---------------- PTX helpers ----------------
__device__ __forceinline__ uint32_t smem_u32(const void* p) {
    uint32_t a;
    asm("{ .reg .u64 t; cvta.to.shared.u64 t, %1; cvt.u32.u64 %0, t; }"
        : "=r"(a) : "l"(p));
    return a;
}

__device__ __forceinline__ void cpa16(uint32_t dst, const void* src) {
    asm volatile("cp.async.cg.shared.global [%0], [%1], 16;"
                 :: "r"(dst), "l"(src) : "memory");
}

#define MBAR_INIT(addr, cnt) \
    asm volatile("mbarrier.init.shared.b64 [%0], %1;" :: "r"(addr), "r"(cnt) : "memory")
#define MBAR_ARRIVE(addr) \
    asm volatile("mbarrier.arrive.shared.b64 _, [%0];" :: "r"(addr) : "memory")
// arrive (counted against the INIT count: .noinc) on completion of this
// thread's prior cp.async ops
#define MBAR_CPA_ARRIVE(addr) \
    asm volatile("cp.async.mbarrier.arrive.noinc.shared.b64 [%0];" :: "r"(addr) : "memory")
#define MBAR_WAIT(addr, par) do {                                             \
    uint32_t _m = (addr); uint32_t _p = (par); uint32_t _d;                   \
    asm volatile("{\n\t.reg .pred p;\n\t"                                     \
        "mbarrier.try_wait.parity.shared.b64 p, [%1], %2;\n\t"                \
        "selp.b32 %0, 1, 0, p;\n\t}"                                          \
        : "=r"(_d) : "r"(_m), "r"(_p) : "memory");                            \
    if (!_d) {                                                                \
        asm volatile("{\n\t.reg .pred P1;\n\t"                                \
            "WL_%=:\n\t"                                                      \
            "mbarrier.try_wait.parity.shared.b64 P1, [%0], %1;\n\t"           \
            "@P1 bra.uni WD_%=;\n\t"                                          \
            "bra.uni WL_%=;\n\t"                                              \
            "WD_%=:\n\t}"                                                     \
            :: "r"(_m), "r"(_p) : "memory");                                  \
    }                                                                         \
} while (0)

__device__ __forceinline__ void ldsm4(uint32_t* r, uint32_t addr) {
    asm volatile("ldmatrix.sync.aligned.m8n8.x4.shared.b16 {%0,%1,%2,%3}, [%4];"
                 : "=r"(r[0]), "=r"(r[1]), "=r"(r[2]), "=r"(r[3]) : "r"(addr));
}

__device__ __forceinline__ void mma16816(float* c, const uint32_t* a, const uint32_t* b) {
    asm volatile(
        "mma.sync.aligned.m16n8k16.row.col.f32.f16.f16.f32 "
        "{%0,%1,%2,%3}, {%4,%5,%6,%7}, {%8,%9}, {%0,%1,%2,%3};"
        : "+f"(c[0]), "+f"(c[1]), "+f"(c[2]), "+f"(c[3])
        : "r"(a[0]), "r"(a[1]), "r"(a[2]), "r"(a[3]), "r"(b[0]), "r"(b[1]));
}

// ---------------- kernel 0: zero counters ----------------
__global__ void zero_cnt_kernel() {
    if (threadIdx.x < EEXP) g_cnt[threadIdx.x] = 0;
}

// ---------------- kernel 1: weight fp32 -> fp16 prepass ----------------
__global__ void __launch_bounds__(256) convert_w_kernel(const float* __restrict__ gw,
                                                        const float* __restrict__ uw,
                                                        const float* __restrict__ dw) {
    size_t n4 = WELEM / 4;
    size_t stride = (size_t)gridDim.x * blockDim.x;
    for (size_t v = (size_t)blockIdx.x * blockDim.x + threadIdx.x; v < n4; v += stride) {
        float4 a = ((const float4*)gw)[v];
        __half2 a0 = __floats2half2_rn(a.x, a.y);
        __half2 a1 = __floats2half2_rn(a.z, a.w);
        *(__half2*)(g_gwh + v * 4)     = a0;
        *(__half2*)(g_gwh + v * 4 + 2) = a1;
        float4 b = ((const float4*)uw)[v];
        __half2 b0 = __floats2half2_rn(b.x, b.y);
        __half2 b1 = __floats2half2_rn(b.z, b.w);
        *(__half2*)(g_uwh + v * 4)     = b0;
        *(__half2*)(g_uwh + v * 4 + 2) = b1;
        float4 d = ((const float4*)dw)[v];
        __half2 d0 = __floats2half2_rn(d.x, d.y);
        __half2 d1 = __floats2half2_rn(d.z, d.w);
        *(__half2*)(g_dwh + v * 4)     = d0;
        *(__half2*)(g_dwh + v * 4 + 2) = d1;
    }
}

// ---------------- kernel 2: router (fp32, exact top-k) ----------------
__global__ void __launch_bounds__(256) router_kernel(const float* __restrict__ x,
                                                     const float* __restrict__ rw) {
    int t = blockIdx.x;
    int warp = threadIdx.x >> 5;
    int lane = threadIdx.x & 31;
    __shared__ float logits[EEXP];

    const float* xr = x + (size_t)t * HDIM;
    const float* wr = rw + (size_t)warp * HDIM;
    float s = 0.f;
    for (int h = lane * 4; h < HDIM; h += 128) {
        float4 xv = *(const float4*)(xr + h);
        float4 wv = *(const float4*)(wr + h);
        s = fmaf(xv.x, wv.x, s);
        s = fmaf(xv.y, wv.y, s);
        s = fmaf(xv.z, wv.z, s);
        s = fmaf(xv.w, wv.w, s);
    }
    #pragma unroll
    for (int o = 16; o; o >>= 1) s += __shfl_down_sync(0xffffffffu, s, o);
    if (lane == 0) logits[warp] = s;
    __syncthreads();

    if (threadIdx.x == 0) {
        int i0 = 0; float v0 = logits[0];
        #pragma unroll
        for (int i = 1; i < EEXP; i++)
            if (logits[i] > v0) { v0 = logits[i]; i0 = i; }
        int i1 = -1; float v1 = -3.0e38f;
        #pragma unroll
        for (int i = 0; i < EEXP; i++) {
            if (i == i0) continue;
            if (logits[i] > v1) { v1 = logits[i]; i1 = i; }
        }
        float e1 = expf(v1 - v0);
        float inv = 1.f / (1.f + e1);
        int s0 = atomicAdd(&g_cnt[i0], 1);
        g_ptok[i0 * T_TOK + s0] = t;
        g_pw  [i0 * T_TOK + s0] = inv;
        int s1 = atomicAdd(&g_cnt[i1], 1);
        g_ptok[i1 * T_TOK + s1] = t;
        g_pw  [i1 * T_TOK + s1] = e1 * inv;
    }
}

// ---------------- kernel 3: gather tokens -> fp16 ----------------
__global__ void __launch_bounds__(128) gather_x_kernel(const float* __restrict__ x) {
    int row = blockIdx.x;                 // e*T_TOK + slot
    int e = row >> 11;
    int slot = row & (T_TOK - 1);
    if (slot >= g_cnt[e]) return;
    const float4* src = (const float4*)(x + (size_t)g_ptok[row] * HDIM);
    size_t ob = (size_t)row * HDIM;
    for (int i = threadIdx.x; i < HDIM / 4; i += 128) {
        float4 v = src[i];
        __half2 h0 = __floats2half2_rn(v.x, v.y);
        __half2 h1 = __floats2half2_rn(v.z, v.w);
        *(__half2*)(g_gah + ob + i * 4)     = h0;
        *(__half2*)(g_gah + ob + i * 4 + 2) = h1;
    }
}

// ---------------- GEMM pipeline layout ----------------
// CTA tile 128(M) x 256(B rows); stage (48KB): A fp16 16K @0 | B fp16 32K @16384
// 4 stages = 196608; barriers @196608: full[4] (+0..24), empty[4] (+32..56)
#define STGSZ   49152u
#define NST     4
#define BAR_OFF 196608u
#define SMEM_GEMM 196864
#define BAR_FULL(sb, s)  ((sb) + BAR_OFF + (uint32_t)(s) * 8)
#define BAR_EMPTY(sb, s) ((sb) + BAR_OFF + 32 + (uint32_t)(s) * 8)

// cp.async a 128x64 fp16 A tile into SW128-swizzled smem (256 threads)
__device__ __forceinline__ void cpa_tileA(uint32_t base,
                                          const __half* __restrict__ A,
                                          size_t stride, int k0, int tid) {
    #pragma unroll
    for (int i = 0; i < 4; i++) {
        int flat = tid + (i << 8);
        int r = flat >> 3, u = flat & 7;
        uint32_t dst = base + r * 128 + ((u ^ (r & 7)) << 4);
        size_t off = (size_t)r * stride + k0 + u * 8;
        cpa16(dst, A + off);
    }
}

// cp.async a 256x64 fp16 B tile, gemm1: interleave gate (even rows) / up (odd)
__device__ __forceinline__ void cpa_tileB1(uint32_t base,
                                           const __half* __restrict__ gwB,
                                           const __half* __restrict__ uwB,
                                           int k0, int tid) {
    #pragma unroll
    for (int i = 0; i < 8; i++) {
        int flat = tid + (i << 8);
        int sr = flat >> 3, u = flat & 7;
        int feat = sr >> 1;
        const __half* src = (sr & 1) ? uwB : gwB;
        uint32_t dst = base + sr * 128 + ((u ^ (sr & 7)) << 4);
        cpa16(dst, src + (size_t)feat * HDIM + k0 + u * 8);
    }
}

// cp.async a 256x64 fp16 B tile, gemm2: contiguous rows of down_w
__device__ __forceinline__ void cpa_tileB2(uint32_t base,
                                           const __half* __restrict__ dwB,
                                           int k0, int tid) {
    #pragma unroll
    for (int i = 0; i < 8; i++) {
        int flat = tid + (i << 8);
        int sr = flat >> 3, u = flat & 7;
        uint32_t dst = base + sr * 128 + ((u ^ (sr & 7)) << 4);
        cpa16(dst, dwB + (size_t)sr * FDIM + k0 + u * 8);
    }
}

// two k16 steps of single-pass fp16 MMA over a 64x64 warp tile
__device__ __forceinline__ void mma_half(uint32_t Ab, uint32_t Bb, int kk0,
                                         int wm, int wn, int lane,
                                         float (&acc)[4][8][4]) {
    #pragma unroll
    for (int ks = 0; ks < 2; ks++) {
        int kk = kk0 + ks * 16;
        uint32_t ah[4][4], bh[8][2];
        int lrow = lane & 15;
        int au = (kk >> 3) + (lane >> 4);          // A smem unit
        #pragma unroll
        for (int mi = 0; mi < 4; mi++) {
            int r = wm * 64 + mi * 16 + lrow;
            uint32_t ad = Ab + r * 128 + ((au ^ (r & 7)) << 4);
            ldsm4(ah[mi], ad);
        }
        int bu = (kk >> 3) + ((lane >> 3) & 1);    // B smem unit
        #pragma unroll
        for (int bi = 0; bi < 4; bi++) {
            int nr = wn * 64 + bi * 16 + ((lane >> 4) << 3) + (lane & 7);
            uint32_t bd = Bb + nr * 128 + ((bu ^ (nr & 7)) << 4);
            uint32_t t[4];
            ldsm4(t, bd);
            bh[2 * bi][0] = t[0]; bh[2 * bi][1] = t[1];
            bh[2 * bi + 1][0] = t[2]; bh[2 * bi + 1][1] = t[3];
        }
        #pragma unroll
        for (int mi = 0; mi < 4; mi++)
            #pragma unroll
            for (int ni = 0; ni < 8; ni++)
                mma16816(acc[mi][ni], ah[mi], bh[ni]);
    }
}

// ---------------- kernel 4: gate/up GEMM (mbarrier pipeline) + SiLU ----------------
// CTA tile 128 x 128f (256 interleaved B rows); 256 threads dual-role
__global__ void __launch_bounds__(256, 1) gemm1_kernel() {
    extern __shared__ char sm[];
    uint32_t sb = smem_u32(sm);
    int e = blockIdx.z;
    int cnt = g_cnt[e];
    int m0 = blockIdx.x << 7;
    if (m0 >= cnt) return;
    int n0f = blockIdx.y << 7;   // 128 f per CTA
    int tid = threadIdx.x, lane = tid & 31, wid = tid >> 5;
    int wm = wid & 1, wn = wid >> 1;   // warp tile 64x64
    const int NC = HDIM / 64;   // 32

    if (tid == 0) {
        #pragma unroll
        for (int s = 0; s < NST; s++) {
            MBAR_INIT(BAR_FULL(sb, s), 256);   // 256 noinc cp.async arrives
            MBAR_INIT(BAR_EMPTY(sb, s), 8);    // 8 consuming warps
        }
    }
    __syncthreads();

    const __half* A = g_gah + ((size_t)e * T_TOK + m0) * HDIM;
    const __half* gwB = g_gwh + ((size_t)e * FDIM + n0f) * HDIM;
    const __half* uwB = g_uwh + ((size_t)e * FDIM + n0f) * HDIM;

    float acc[4][8][4];
    #pragma unroll
    for (int a = 0; a < 4; a++)
        #pragma unroll
        for (int b = 0; b < 8; b++)
            #pragma unroll
            for (int c = 0; c < 4; c++) acc[a][b][c] = 0.f;

    int ps = 0, pph = 1;   // producer cursor
    int cs = 0, cph = 0;   // consumer cursor
    for (int c = 0; c < NC + 2; c++) {
        uint32_t Ab = sb + cs * STGSZ;
        uint32_t Bb = Ab + 16384u;
        if (c >= 2) {
            MBAR_WAIT(BAR_FULL(sb, cs), cph);
            mma_half(Ab, Bb, 0, wm, wn, lane, acc);
        }
        if (c < NC) {
            MBAR_WAIT(BAR_EMPTY(sb, ps), pph);
            uint32_t base = sb + ps * STGSZ;
            cpa_tileA(base, A, HDIM, c << 6, tid);
            cpa_tileB1(base + 16384u, gwB, uwB, c << 6, tid);
            MBAR_CPA_ARRIVE(BAR_FULL(sb, ps));
            if (++ps == NST) { ps = 0; pph ^= 1; }
        }
        if (c >= 2) {
            mma_half(Ab, Bb, 32, wm, wn, lane, acc);
            __syncwarp();
            if (lane == 0) MBAR_ARRIVE(BAR_EMPTY(sb, cs));
            if (++cs == NST) { cs = 0; cph ^= 1; }
        }
    }

    // epilogue: acc cols (c0,c1) = (gate_j, up_j); h = silu(g)*u -> fp16
    #pragma unroll
    for (int mi = 0; mi < 4; mi++)
        #pragma unroll
        for (int rh = 0; rh < 2; rh++) {
            int row = wm * 64 + mi * 16 + (lane >> 2) + rh * 8;
            int slot = m0 + row;
            if (slot < cnt) {
                size_t hb = ((size_t)e * T_TOK + slot) * FDIM + n0f;
                #pragma unroll
                for (int ni = 0; ni < 8; ni++) {
                    float g = acc[mi][ni][rh * 2 + 0];
                    float u = acc[mi][ni][rh * 2 + 1];
                    float h = u * g / (1.f + __expf(-g));
                    int j = wn * 32 + ni * 4 + (lane & 3);
                    g_hbh[hb + j] = __float2half_rn(h);
                }
            }
        }
}

// ---------------- kernel 5: down GEMM (mbarrier pipeline) + weighted scatter ----------------
// CTA tile 128 x 256; 256 threads dual-role
__global__ void __launch_bounds__(256, 1) gemm2_kernel(float* __restrict__ out) {
    extern __shared__ char sm[];
    uint32_t sb = smem_u32(sm);
    int e = blockIdx.z;
    int cnt = g_cnt[e];
    int m0 = blockIdx.x << 7;
    if (m0 >= cnt) return;
    int n0 = blockIdx.y << 8;   // 256 h-cols per CTA
    int tid = threadIdx.x, lane = tid & 31, wid = tid >> 5;
    int wm = wid & 1, wn = wid >> 1;
    const int NC = FDIM / 64;   // 86

    if (tid == 0) {
        #pragma unroll
        for (int s = 0; s < NST; s++) {
            MBAR_INIT(BAR_FULL(sb, s), 256);
            MBAR_INIT(BAR_EMPTY(sb, s), 8);
        }
    }
    __syncthreads();

    const __half* A = g_hbh + ((size_t)e * T_TOK + m0) * FDIM;
    const __half* dwB = g_dwh + ((size_t)e * HDIM + n0) * FDIM;

    float acc[4][8][4];
    #pragma unroll
    for (int a = 0; a < 4; a++)
        #pragma unroll
        for (int b = 0; b < 8; b++)
            #pragma unroll
            for (int c = 0; c < 4; c++) acc[a][b][c] = 0.f;

    int ps = 0, pph = 1;
    int cs = 0, cph = 0;
    for (int c = 0; c < NC + 2; c++) {
        uint32_t Ab = sb + cs * STGSZ;
        uint32_t Bb = Ab + 16384u;
        if (c >= 2) {
            MBAR_WAIT(BAR_FULL(sb, cs), cph);
            mma_half(Ab, Bb, 0, wm, wn, lane, acc);
        }
        if (c < NC) {
            MBAR_WAIT(BAR_EMPTY(sb, ps), pph);
            uint32_t base = sb + ps * STGSZ;
            cpa_tileA(base, A, FDIM, c << 6, tid);
            cpa_tileB2(base + 16384u, dwB, c << 6, tid);
            MBAR_CPA_ARRIVE(BAR_FULL(sb, ps));
            if (++ps == NST) { ps = 0; pph ^= 1; }
        }
        if (c >= 2) {
            mma_half(Ab, Bb, 32, wm, wn, lane, acc);
            __syncwarp();
            if (lane == 0) MBAR_ARRIVE(BAR_EMPTY(sb, cs));
            if (++cs == NST) { cs = 0; cph ^= 1; }
        }
    }

    // epilogue: weighted atomic scatter to out
    #pragma unroll
    for (int mi = 0; mi < 4; mi++)
        #pragma unroll
        for (int rh = 0; rh < 2; rh++) {
            int row = wm * 64 + mi * 16 + (lane >> 2) + rh * 8;
            int slot = m0 + row;
            if (slot < cnt) {
                int tok = g_ptok[e * T_TOK + slot];
                float w = g_pw[e * T_TOK + slot];
                float* orow = out + (size_t)tok * HDIM + n0;
                #pragma unroll
                for (int ni = 0; ni < 8; ni++) {
                    int col = wn * 64 + ni * 8 + 2 * (lane & 3);
                    atomicAdd(orow + col,     acc[mi][ni][rh * 2 + 0] * w);
                    atomicAdd(orow + col + 1, acc[mi][ni][rh * 2 + 1] * w);
                }
            }
        }
}

// ---------------- launch ----------------
extern "C" void kernel_launch(void* const* d_in, const int* in_sizes, int n_in,
                              void* d_out, int out_size) {
    const float* x  = (const float*)d_in[0];   // [B,S,H]
    const float* rw = (const float*)d_in[1];   // [E,H]
    const float* gw = (const float*)d_in[2];   // [E,F,H]
    const float* uw = (const float*)d_in[3];   // [E,F,H]
    const float* dw = (const float*)d_in[4];   // [E,H,F]
    float* out = (float*)d_out;

    cudaFuncSetAttribute(gemm1_kernel, cudaFuncAttributeMaxDynamicSharedMemorySize, SMEM_GEMM);
    cudaFuncSetAttribute(gemm2_kernel, cudaFuncAttributeMaxDynamicSharedMemorySize, SMEM_GEMM);

    cudaMemsetAsync(out, 0, (size_t)out_size * sizeof(float));
    zero_cnt_kernel<<<1, 32>>>();
    convert_w_kernel<<<8192, 256>>>(gw, uw, dw);
    router_kernel<<<T_TOK, 256>>>(x, rw);
    gather_x_kernel<<<EEXP * T_TOK, 128>>>(x);
    gemm1_kernel<<<dim3(16, FDIM / 128, EEXP), 256, SMEM_GEMM>>>();
    gemm2_kernel<<<dim3(16, HDIM / 256, EEXP), 256, SMEM_GEMM>>>(out);
}

// round 14
// speedup vs baseline: 1.0452x; 1.0214x over previous
#include <cuda_runtime.h>
#include <cuda_fp16.h>
#include <cstdint>
#include <math.h>

// ---------------- problem constants ----------------
#define T_TOK 2048
#define HDIM  2048
#define FDIM  5504
#define EEXP  8

// ---------------- device scratch (static, no allocation) ----------------
__device__ int   g_cnt[EEXP];
__device__ int   g_ptok[EEXP * T_TOK];
__device__ float g_pw[EEXP * T_TOK];

#define WELEM  ((size_t)EEXP * (size_t)FDIM * (size_t)HDIM)
#define GAELEM ((size_t)EEXP * (size_t)T_TOK * (size_t)HDIM)
#define HBELEM ((size_t)EEXP * (size_t)T_TOK * (size_t)FDIM)
__device__ __align__(16) __half g_dwh[WELEM];  // down w fp16 [E,H,F] (converted by gemm1)
__device__ __align__(16) __half g_gah[GAELEM]; // gathered x (fp16)
__device__ __align__(16) __half g_hbh[HBELEM]; // silu(g)*u (fp16)

// ---------------- PTX helpers ----------------
__device__ __forceinline__ uint32_t smem_u32(const void* p) {
    uint32_t a;
    asm("{ .reg .u64 t; cvta.to.shared.u64 t, %1; cvt.u32.u64 %0, t; }"
        : "=r"(a) : "l"(p));
    return a;
}

__device__ __forceinline__ void cpa16(uint32_t dst, const void* src) {
    asm volatile("cp.async.cg.shared.global [%0], [%1], 16;"
                 :: "r"(dst), "l"(src) : "memory");
}

#define MBAR_INIT(addr, cnt) \
    asm volatile("mbarrier.init.shared.b64 [%0], %1;" :: "r"(addr), "r"(cnt) : "memory")
#define MBAR_ARRIVE(addr) \
    asm volatile("mbarrier.arrive.shared.b64 _, [%0];" :: "r"(addr) : "memory")
// arrive (counted against the INIT count: .noinc) on completion of this
// thread's prior cp.async ops
#define MBAR_CPA_ARRIVE(addr) \
    asm volatile("cp.async.mbarrier.arrive.noinc.shared.b64 [%0];" :: "r"(addr) : "memory")
#define MBAR_WAIT(addr, par) do {                                             \
    uint32_t _m = (addr); uint32_t _p = (par); uint32_t _d;                   \
    asm volatile("{\n\t.reg .pred p;\n\t"                                     \
        "mbarrier.try_wait.parity.shared.b64 p, [%1], %2;\n\t"                \
        "selp.b32 %0, 1, 0, p;\n\t}"                                          \
        : "=r"(_d) : "r"(_m), "r"(_p) : "memory");                            \
    if (!_d) {                                                                \
        asm volatile("{\n\t.reg .pred P1;\n\t"                                \
            "WL_%=:\n\t"                                                      \
            "mbarrier.try_wait.parity.shared.b64 P1, [%0], %1;\n\t"           \
            "@P1 bra.uni WD_%=;\n\t"                                          \
            "bra.uni WL_%=;\n\t"                                              \
            "WD_%=:\n\t}"                                                     \
            :: "r"(_m), "r"(_p) : "memory");                                  \
    }                                                                         \
} while (0)

__device__ __forceinline__ void ldsm4(uint32_t* r, uint32_t addr) {
    asm volatile("ldmatrix.sync.aligned.m8n8.x4.shared.b16 {%0,%1,%2,%3}, [%4];"
                 : "=r"(r[0]), "=r"(r[1]), "=r"(r[2]), "=r"(r[3]) : "r"(addr));
}

__device__ __forceinline__ void mma16816(float* c, const uint32_t* a, const uint32_t* b) {
    asm volatile(
        "mma.sync.aligned.m16n8k16.row.col.f32.f16.f16.f32 "
        "{%0,%1,%2,%3}, {%4,%5,%6,%7}, {%8,%9}, {%0,%1,%2,%3};"
        : "+f"(c[0]), "+f"(c[1]), "+f"(c[2]), "+f"(c[3])
        : "r"(a[0]), "r"(a[1]), "r"(a[2]), "r"(a[3]), "r"(b[0]), "r"(b[1]));
}

// ---------------- kernel 0: zero counters ----------------
__global__ void zero_cnt_kernel() {
    if (threadIdx.x < EEXP) g_cnt[threadIdx.x] = 0;
}

// ---------------- kernel 1: router (fp32, exact top-k) ----------------
__global__ void __launch_bounds__(256) router_kernel(const float* __restrict__ x,
                                                     const float* __restrict__ rw) {
    int t = blockIdx.x;
    int warp = threadIdx.x >> 5;
    int lane = threadIdx.x & 31;
    __shared__ float logits[EEXP];

    const float* xr = x + (size_t)t * HDIM;
    const float* wr = rw + (size_t)warp * HDIM;
    float s = 0.f;
    for (int h = lane * 4; h < HDIM; h += 128) {
        float4 xv = *(const float4*)(xr + h);
        float4 wv = *(const float4*)(wr + h);
        s = fmaf(xv.x, wv.x, s);
        s = fmaf(xv.y, wv.y, s);
        s = fmaf(xv.z, wv.z, s);
        s = fmaf(xv.w, wv.w, s);
    }
    #pragma unroll
    for (int o = 16; o; o >>= 1) s += __shfl_down_sync(0xffffffffu, s, o);
    if (lane == 0) logits[warp] = s;
    __syncthreads();

    if (threadIdx.x == 0) {
        int i0 = 0; float v0 = logits[0];
        #pragma unroll
        for (int i = 1; i < EEXP; i++)
            if (logits[i] > v0) { v0 = logits[i]; i0 = i; }
        int i1 = -1; float v1 = -3.0e38f;
        #pragma unroll
        for (int i = 0; i < EEXP; i++) {
            if (i == i0) continue;
            if (logits[i] > v1) { v1 = logits[i]; i1 = i; }
        }
        float e1 = expf(v1 - v0);
        float inv = 1.f / (1.f + e1);
        int s0 = atomicAdd(&g_cnt[i0], 1);
        g_ptok[i0 * T_TOK + s0] = t;
        g_pw  [i0 * T_TOK + s0] = inv;
        int s1 = atomicAdd(&g_cnt[i1], 1);
        g_ptok[i1 * T_TOK + s1] = t;
        g_pw  [i1 * T_TOK + s1] = e1 * inv;
    }
}

// ---------------- kernel 2: gather tokens -> fp16 ----------------
__global__ void __launch_bounds__(128) gather_x_kernel(const float* __restrict__ x) {
    int row = blockIdx.x;                 // e*T_TOK + slot
    int e = row >> 11;
    int slot = row & (T_TOK - 1);
    if (slot >= g_cnt[e]) return;
    const float4* src = (const float4*)(x + (size_t)g_ptok[row] * HDIM);
    size_t ob = (size_t)row * HDIM;
    for (int i = threadIdx.x; i < HDIM / 4; i += 128) {
        float4 v = src[i];
        __half2 h0 = __floats2half2_rn(v.x, v.y);
        __half2 h1 = __floats2half2_rn(v.z, v.w);
        *(__half2*)(g_gah + ob + i * 4)     = h0;
        *(__half2*)(g_gah + ob + i * 4 + 2) = h1;
    }
}

// ================= gemm1: R9 configuration =================
// stage (32KB): A fp16 16K @0 | B fp16 16K @16384; 4 stages
#define G1_STGSZ   32768u
#define G1_NST     4
#define G1_BAROFF  131072u
#define G1_SMEM    131328
#define G1_BFULL(sb, s)  ((sb) + G1_BAROFF + (uint32_t)(s) * 8)
#define G1_BEMPTY(sb, s) ((sb) + G1_BAROFF + 32 + (uint32_t)(s) * 8)

// cp.async a 128x64 fp16 A tile into SW128-swizzled smem (256 threads)
__device__ __forceinline__ void cpa_tileA(uint32_t base,
                                          const __half* __restrict__ A,
                                          size_t stride, int k0, int tid) {
    #pragma unroll
    for (int i = 0; i < 4; i++) {
        int flat = tid + (i << 8);
        int r = flat >> 3, u = flat & 7;
        uint32_t dst = base + r * 128 + ((u ^ (r & 7)) << 4);
        size_t off = (size_t)r * stride + k0 + u * 8;
        cpa16(dst, A + off);
    }
}

// store fp32 regs as single-rounded fp16 into swizzled B tile (interleaving
// gate/up rows: smem row = 2*r (gate) / 2*r+1 (up)) -- 128 rows
__device__ __forceinline__ void sts_B1(char* sm, uint32_t sboff, const float4* br, int tid) {
    #pragma unroll
    for (int i = 0; i < 8; i++) {
        int flat = tid + (i << 8);
        int row = flat >> 4, c4 = flat & 15;
        int sr = (row < 64) ? (row << 1) : (((row - 64) << 1) + 1);
        uint32_t off = sboff + sr * 128 + (((c4 >> 1) ^ (sr & 7)) << 4) + ((c4 & 1) << 3);
        float4 v = br[i];
        __half2 h0 = __floats2half2_rn(v.x, v.y);
        __half2 h1 = __floats2half2_rn(v.z, v.w);
        uint2 hp = make_uint2(*(uint32_t*)&h0, *(uint32_t*)&h1);
        *(uint2*)(sm + off) = hp;
    }
}

// two k16 steps of single-pass fp16 MMA over a 64x32 warp tile (gemm1)
__device__ __forceinline__ void mma_half_32(uint32_t Ab, uint32_t Bb, int kk0,
                                            int wm, int wn, int lane,
                                            float (&acc)[4][4][4]) {
    #pragma unroll
    for (int ks = 0; ks < 2; ks++) {
        int kk = kk0 + ks * 16;
        uint32_t ah[4][4], bh[4][2];
        int lrow = lane & 15;
        int au = (kk >> 3) + (lane >> 4);
        #pragma unroll
        for (int mi = 0; mi < 4; mi++) {
            int r = wm * 64 + mi * 16 + lrow;
            uint32_t ad = Ab + r * 128 + ((au ^ (r & 7)) << 4);
            ldsm4(ah[mi], ad);
        }
        int bu = (kk >> 3) + ((lane >> 3) & 1);
        #pragma unroll
        for (int bi = 0; bi < 2; bi++) {
            int nr = wn * 32 + bi * 16 + ((lane >> 4) << 3) + (lane & 7);
            uint32_t bd = Bb + nr * 128 + ((bu ^ (nr & 7)) << 4);
            uint32_t t[4];
            ldsm4(t, bd);
            bh[2 * bi][0] = t[0]; bh[2 * bi][1] = t[1];
            bh[2 * bi + 1][0] = t[2]; bh[2 * bi + 1][1] = t[3];
        }
        #pragma unroll
        for (int mi = 0; mi < 4; mi++)
            #pragma unroll
            for (int ni = 0; ni < 4; ni++)
                mma16816(acc[mi][ni], ah[mi], bh[ni]);
    }
}

// B fp32 register loads (8 float4 per thread), gemm1 (gate|up)
__device__ __forceinline__ void ldg_B1(float4* br, const float* __restrict__ gwB,
                                       const float* __restrict__ uwB, int k0, int tid) {
    #pragma unroll
    for (int i = 0; i < 8; i++) {
        int flat = tid + (i << 8);
        int row = flat >> 4, c4 = flat & 15;
        const float* s = (row < 64) ? (gwB + (size_t)row * HDIM)
                                    : (uwB + (size_t)(row - 64) * HDIM);
        br[i] = *(const float4*)(s + k0 + c4 * 4);
    }
}

// ---------------- kernel 3: gate/up GEMM + SiLU + dw side-convert ----------------
// R9 config: CTA 128M x 64F (128 interleaved B rows), warp tile 64x32.
// Side-job: each of the 11008 CTAs converts 2048 float4 of down_w -> g_dwh.
// 11008 * 2048 = 22,544,384 float4 = WELEM/4 exactly.
__global__ void __launch_bounds__(256, 1) gemm1_kernel(const float* __restrict__ gw,
                                                       const float* __restrict__ uw,
                                                       const float* __restrict__ dw) {
    extern __shared__ char sm[];
    uint32_t sb = smem_u32(sm);
    int tid = threadIdx.x, lane = tid & 31, wid = tid >> 5;

    // ---- dw conversion side-job (runs in every CTA, before any early return)
    {
        int cid = (blockIdx.z * gridDim.y + blockIdx.y) * gridDim.x + blockIdx.x;
        size_t base = (size_t)cid * 2048 + tid;   // float4 index
        const float4* src = (const float4*)dw;
        #pragma unroll
        for (int i = 0; i < 8; i++) {
            size_t v = base + (size_t)i * 256;
            float4 a = src[v];
            __half2 h0 = __floats2half2_rn(a.x, a.y);
            __half2 h1 = __floats2half2_rn(a.z, a.w);
            uint2 hp = make_uint2(*(uint32_t*)&h0, *(uint32_t*)&h1);
            *(uint2*)(g_dwh + v * 4) = hp;
        }
    }

    int e = blockIdx.z;
    int cnt = g_cnt[e];
    int m0 = blockIdx.x << 7;
    if (m0 >= cnt) return;
    int n0f = blockIdx.y << 6;
    int wm = wid & 1, wn = wid >> 1;
    const int NC = HDIM / 64;   // 32

    if (tid == 0) {
        #pragma unroll
        for (int s = 0; s < G1_NST; s++) {
            MBAR_INIT(G1_BFULL(sb, s), 512);   // 256 noinc cp.async arrives + 256 sts arrives
            MBAR_INIT(G1_BEMPTY(sb, s), 8);    // 8 consuming warps
        }
    }
    __syncthreads();

    const __half* A = g_gah + ((size_t)e * T_TOK + m0) * HDIM;
    const float* gwB = gw + ((size_t)e * FDIM + n0f) * HDIM;
    const float* uwB = uw + ((size_t)e * FDIM + n0f) * HDIM;

    float acc[4][4][4];
    #pragma unroll
    for (int a = 0; a < 4; a++)
        #pragma unroll
        for (int b = 0; b < 4; b++)
            #pragma unroll
            for (int c = 0; c < 4; c++) acc[a][b][c] = 0.f;

    float4 br[8];
    ldg_B1(br, gwB, uwB, 0, tid);

    int ps = 0, pph = 1;   // producer cursor
    int cs = 0, cph = 0;   // consumer cursor
    for (int c = 0; c < NC + 2; c++) {
        uint32_t Ab = sb + cs * G1_STGSZ;
        uint32_t Bb = Ab + 16384u;
        if (c >= 2) {
            MBAR_WAIT(G1_BFULL(sb, cs), cph);
            mma_half_32(Ab, Bb, 0, wm, wn, lane, acc);
        }
        if (c < NC) {
            MBAR_WAIT(G1_BEMPTY(sb, ps), pph);
            uint32_t base = sb + ps * G1_STGSZ;
            cpa_tileA(base, A, HDIM, c << 6, tid);
            MBAR_CPA_ARRIVE(G1_BFULL(sb, ps));
            sts_B1(sm, ps * G1_STGSZ + 16384u, br, tid);
            MBAR_ARRIVE(G1_BFULL(sb, ps));
            if (++ps == G1_NST) { ps = 0; pph ^= 1; }
            if (c + 1 < NC) ldg_B1(br, gwB, uwB, (c + 1) << 6, tid);
        }
        if (c >= 2) {
            mma_half_32(Ab, Bb, 32, wm, wn, lane, acc);
            __syncwarp();
            if (lane == 0) MBAR_ARRIVE(G1_BEMPTY(sb, cs));
            if (++cs == G1_NST) { cs = 0; cph ^= 1; }
        }
    }

    // epilogue: cols 2j/2j+1 = (gate_j, up_j); h = silu(g)*u -> fp16
    #pragma unroll
    for (int mi = 0; mi < 4; mi++)
        #pragma unroll
        for (int rh = 0; rh < 2; rh++) {
            int row = wm * 64 + mi * 16 + (lane >> 2) + rh * 8;
            int slot = m0 + row;
            if (slot < cnt) {
                size_t hb = ((size_t)e * T_TOK + slot) * FDIM + n0f;
                #pragma unroll
                for (int ni = 0; ni < 4; ni++) {
                    float g = acc[mi][ni][rh * 2 + 0];
                    float u = acc[mi][ni][rh * 2 + 1];
                    float h = u * g / (1.f + __expf(-g));
                    int j = wn * 16 + ni * 4 + (lane & 3);
                    g_hbh[hb + j] = __float2half_rn(h);
                }
            }
        }
}

// ================= gemm2: R11 configuration =================
// CTA tile 128(M) x 256(B rows); stage (48KB): A 16K @0 | B 32K @16384; 4 stages
#define G2_STGSZ   49152u
#define G2_NST     4
#define G2_BAROFF  196608u
#define G2_SMEM    196864
#define G2_BFULL(sb, s)  ((sb) + G2_BAROFF + (uint32_t)(s) * 8)
#define G2_BEMPTY(sb, s) ((sb) + G2_BAROFF + 32 + (uint32_t)(s) * 8)

// cp.async a 256x64 fp16 B tile: contiguous rows of g_dwh
__device__ __forceinline__ void cpa_tileB2(uint32_t base,
                                           const __half* __restrict__ dwB,
                                           int k0, int tid) {
    #pragma unroll
    for (int i = 0; i < 8; i++) {
        int flat = tid + (i << 8);
        int sr = flat >> 3, u = flat & 7;
        uint32_t dst = base + sr * 128 + ((u ^ (sr & 7)) << 4);
        cpa16(dst, dwB + (size_t)sr * FDIM + k0 + u * 8);
    }
}

// two k16 steps of single-pass fp16 MMA over a 64x64 warp tile (gemm2)
__device__ __forceinline__ void mma_half_64(uint32_t Ab, uint32_t Bb, int kk0,
                                            int wm, int wn, int lane,
                                            float (&acc)[4][8][4]) {
    #pragma unroll
    for (int ks = 0; ks < 2; ks++) {
        int kk = kk0 + ks * 16;
        uint32_t ah[4][4], bh[8][2];
        int lrow = lane & 15;
        int au = (kk >> 3) + (lane >> 4);
        #pragma unroll
        for (int mi = 0; mi < 4; mi++) {
            int r = wm * 64 + mi * 16 + lrow;
            uint32_t ad = Ab + r * 128 + ((au ^ (r & 7)) << 4);
            ldsm4(ah[mi], ad);
        }
        int bu = (kk >> 3) + ((lane >> 3) & 1);
        #pragma unroll
        for (int bi = 0; bi < 4; bi++) {
            int nr = wn * 64 + bi * 16 + ((lane >> 4) << 3) + (lane & 7);
            uint32_t bd = Bb + nr * 128 + ((bu ^ (nr & 7)) << 4);
            uint32_t t[4];
            ldsm4(t, bd);
            bh[2 * bi][0] = t[0]; bh[2 * bi][1] = t[1];
            bh[2 * bi + 1][0] = t[2]; bh[2 * bi + 1][1] = t[3];
        }
        #pragma unroll
        for (int mi = 0; mi < 4; mi++)
            #pragma unroll
            for (int ni = 0; ni < 8; ni++)
                mma16816(acc[mi][ni], ah[mi], bh[ni]);
    }
}

// ---------------- kernel 4: down GEMM (pure cp.async) + weighted scatter ----------------
__global__ void __launch_bounds__(256, 1) gemm2_kernel(float* __restrict__ out) {
    extern __shared__ char sm[];
    uint32_t sb = smem_u32(sm);
    int e = blockIdx.z;
    int cnt = g_cnt[e];
    int m0 = blockIdx.x << 7;
    if (m0 >= cnt) return;
    int n0 = blockIdx.y << 8;   // 256 h-cols per CTA
    int tid = threadIdx.x, lane = tid & 31, wid = tid >> 5;
    int wm = wid & 1, wn = wid >> 1;
    const int NC = FDIM / 64;   // 86

    if (tid == 0) {
        #pragma unroll
        for (int s = 0; s < G2_NST; s++) {
            MBAR_INIT(G2_BFULL(sb, s), 256);   // 256 noinc cp.async arrives
            MBAR_INIT(G2_BEMPTY(sb, s), 8);
        }
    }
    __syncthreads();

    const __half* A = g_hbh + ((size_t)e * T_TOK + m0) * FDIM;
    const __half* dwB = g_dwh + ((size_t)e * HDIM + n0) * FDIM;

    float acc[4][8][4];
    #pragma unroll
    for (int a = 0; a < 4; a++)
        #pragma unroll
        for (int b = 0; b < 8; b++)
            #pragma unroll
            for (int c = 0; c < 4; c++) acc[a][b][c] = 0.f;

    int ps = 0, pph = 1;
    int cs = 0, cph = 0;
    for (int c = 0; c < NC + 2; c++) {
        uint32_t Ab = sb + cs * G2_STGSZ;
        uint32_t Bb = Ab + 16384u;
        if (c >= 2) {
            MBAR_WAIT(G2_BFULL(sb, cs), cph);
            mma_half_64(Ab, Bb, 0, wm, wn, lane, acc);
        }
        if (c < NC) {
            MBAR_WAIT(G2_BEMPTY(sb, ps), pph);
            uint32_t base = sb + ps * G2_STGSZ;
            cpa_tileA(base, A, FDIM, c << 6, tid);
            cpa_tileB2(base + 16384u, dwB, c << 6, tid);
            MBAR_CPA_ARRIVE(G2_BFULL(sb, ps));
            if (++ps == G2_NST) { ps = 0; pph ^= 1; }
        }
        if (c >= 2) {
            mma_half_64(Ab, Bb, 32, wm, wn, lane, acc);
            __syncwarp();
            if (lane == 0) MBAR_ARRIVE(G2_BEMPTY(sb, cs));
            if (++cs == G2_NST) { cs = 0; cph ^= 1; }
        }
    }

    // epilogue: weighted atomic scatter to out
    #pragma unroll
    for (int mi = 0; mi < 4; mi++)
        #pragma unroll
        for (int rh = 0; rh < 2; rh++) {
            int row = wm * 64 + mi * 16 + (lane >> 2) + rh * 8;
            int slot = m0 + row;
            if (slot < cnt) {
                int tok = g_ptok[e * T_TOK + slot];
                float w = g_pw[e * T_TOK + slot];
                float* orow = out + (size_t)tok * HDIM + n0;
                #pragma unroll
                for (int ni = 0; ni < 8; ni++) {
                    int col = wn * 64 + ni * 8 + 2 * (lane & 3);
                    atomicAdd(orow + col,     acc[mi][ni][rh * 2 + 0] * w);
                    atomicAdd(orow + col + 1, acc[mi][ni][rh * 2 + 1] * w);
                }
            }
        }
}

// ---------------- launch ----------------
extern "C" void kernel_launch(void* const* d_in, const int* in_sizes, int n_in,
                              void* d_out, int out_size) {
    const float* x  = (const float*)d_in[0];   // [B,S,H]
    const float* rw = (const float*)d_in[1];   // [E,H]
    const float* gw = (const float*)d_in[2];   // [E,F,H]
    const float* uw = (const float*)d_in[3];   // [E,F,H]
    const float* dw = (const float*)d_in[4];   // [E,H,F]
    float* out = (float*)d_out;

    cudaFuncSetAttribute(gemm1_kernel, cudaFuncAttributeMaxDynamicSharedMemorySize, G1_SMEM);
    cudaFuncSetAttribute(gemm2_kernel, cudaFuncAttributeMaxDynamicSharedMemorySize, G2_SMEM);

    cudaMemsetAsync(out, 0, (size_t)out_size * sizeof(float));
    zero_cnt_kernel<<<1, 32>>>();
    router_kernel<<<T_TOK, 256>>>(x, rw);
    gather_x_kernel<<<EEXP * T_TOK, 128>>>(x);
    gemm1_kernel<<<dim3(16, FDIM / 64, EEXP), 256, G1_SMEM>>>(gw, uw, dw);
    gemm2_kernel<<<dim3(16, HDIM / 256, EEXP), 256, G2_SMEM>>>(out);
}